// round 14
// baseline (speedup 1.0000x reference)
#include <cuda_runtime.h>

#define NND 2048
#define NF  32
#define NC  3
#define NH  35
#define H1  64
#define H2  32
#define GRID_N 272u

// ---------------- scratch (device globals, no allocs) ----------------
__device__ __align__(16) float g_invn[NND];
__device__ __align__(16) float g_s[NND * NF];          // x^2 * invnorm
__device__ __align__(16) float g_partA[256 * NF];      // chunk sums of g_s (8-row chunks)
__device__ __align__(16) float g_credp[16 * NND * 3];  // per-i-tile centroid partials
__device__ __align__(16) float g_h1[NND * H1];
__device__ __align__(16) float g_partB[256 * H1];      // chunk sums of h1 (8-row chunks)
__device__ __align__(16) float g_A[NND * H2];          // h2 @ Wm1[0:32] + bm1
__device__ __align__(16) float g_B[NND * H2];          // h2 @ Wm1[32:64]
__device__ __align__(16) float g_wd[H2];
__device__ float g_bd;

// barrier counters (monotonic across graph replays; no reset needed)
__device__ unsigned g_bar1, g_bar2, g_bar3;

__device__ __forceinline__ void gbarrier(unsigned* ctr) {
    __syncthreads();
    if (threadIdx.x == 0) {
        __threadfence();
        unsigned ticket = atomicAdd(ctr, 1u);
        unsigned target = (ticket / GRID_N + 1u) * GRID_N;
        while (atomicAdd(ctr, 0u) < target) { __nanosleep(32); }
        __threadfence();
    }
    __syncthreads();
}

// ---------------- shared-memory union across phases ----------------
struct SP1a { float sm[16][33]; };
struct SP1b { float sc[3][128]; };
struct SP2 {
    float sWs[NH][H1];
    float sWn[NH][H1];
    float sg[8][33];
    float sredA[8][NF];
    float soff[NF];
    float scred[8][3];
    float sH[8][36];
    float sN[8][36];
    float sRed[8][H1 + 1];
};
struct SP3 {
    float sWs2[H1][H2];
    float sWn2[H1][H2];
    float sWm1[H1][H2];
    float sHx[8][H1 + 1];
    float sP1[8][H1 + 1];
    float h2s[8][H2 + 1];
    float soffB[H1];
    float red[8][H1];
};
struct SP4 {
    float sAt[H2][68];    // k-major A tile (64 i + pad)
    float sBt[H2][132];   // k-major B tile (128 j + pad)
    float swd[H2];
    float sbd;
};
union SU { SP1a p1a; SP1b p1b; SP2 p2; SP3 p3; SP4 p4; };

// ================ single fused kernel: 272 blocks x 512 threads ================
__global__ void __launch_bounds__(512, 2) k_fused(
    const float* __restrict__ x, const float* __restrict__ cent,
    const float* __restrict__ Ws1, const float* __restrict__ Wn1,
    const float* __restrict__ b1,
    const float* __restrict__ Ws2, const float* __restrict__ Wn2,
    const float* __restrict__ b2,
    const float* __restrict__ Wm1, const float* __restrict__ bm1,
    const float* __restrict__ Wm2, const float* __restrict__ bm2,
    float* __restrict__ out)
{
    __shared__ SU su;
    int blk = blockIdx.x;
    int t = threadIdx.x;

    // ================= Phase 1 =================
    if (blk < 128) {
        // normsum: 16 nodes/block; emit TWO 8-row chunk partials
        int f = t & 31, r = t >> 5;
        int node = blk * 16 + r;
        float v = x[node * NF + f];
        float sq = v * v;
        float sum = sq;
#pragma unroll
        for (int m = 16; m > 0; m >>= 1) sum += __shfl_xor_sync(0xffffffffu, sum, m);
        float invn = rsqrtf(sum);
        if (f == 0) g_invn[node] = invn;
        float s = sq * invn;
        g_s[node * NF + f] = s;
        su.p1a.sm[r][f] = s;
        __syncthreads();
        // half-local tree reduce (rows 0-7 and 8-15 independently)
        if ((r & 7) < 4) su.p1a.sm[r][f] += su.p1a.sm[r + 4][f];
        __syncthreads();
        if ((r & 7) < 2) su.p1a.sm[r][f] += su.p1a.sm[r + 2][f];
        __syncthreads();
        if ((r & 7) == 0)
            g_partA[(2 * blk + (r >> 3)) * NF + f] = su.p1a.sm[r][f] + su.p1a.sm[r + 1][f];
    } else if (blk < 264) {
        // centroid |diff| tile partials: 136 triangular 128x128 tiles
        int rr = blk - 128;
        int bj = 0;
        while (rr >= bj + 1) { rr -= bj + 1; bj++; }
        int bi = rr;  // bi <= bj
        int i0 = bi * 128;
        if (t < 128) {
            su.p1b.sc[0][t] = cent[(i0 + t) * 3 + 0];
            su.p1b.sc[1][t] = cent[(i0 + t) * 3 + 1];
            su.p1b.sc[2][t] = cent[(i0 + t) * 3 + 2];
        }
        __syncthreads();
        if (t < 128) {
            int j = bj * 128 + t;
            float cj0 = cent[j * 3 + 0], cj1 = cent[j * 3 + 1], cj2 = cent[j * 3 + 2];
            int lim = j - i0;
            if (lim > 128) lim = 128;
            float t0 = 0.f, t1 = 0.f, t2 = 0.f;
#pragma unroll 4
            for (int il = 0; il < lim; il++) {
                float a = su.p1b.sc[0][il], b = su.p1b.sc[1][il], c = su.p1b.sc[2][il];
                t0 += a * fabsf(a - cj0);
                t1 += b * fabsf(b - cj1);
                t2 += c * fabsf(c - cj2);
            }
            size_t o = ((size_t)bi * NND + j) * 3;
            g_credp[o + 0] = t0;
            g_credp[o + 1] = t1;
            g_credp[o + 2] = t2;
        }
    }

    gbarrier(&g_bar1);

    // ================= Phase 2: h1 GEMM (blocks 0..255, 8 nodes each) =================
    if (blk < 256) {
        int nbase = blk * 8;
        for (int idx = t; idx < NH * H1; idx += 512) {
            su.p2.sWs[idx / H1][idx % H1] = Ws1[idx];
            su.p2.sWn[idx / H1][idx % H1] = Wn1[idx];
        }
        {
            int f = t & 31, n = t >> 5;
            if (n < 8) su.p2.sg[n][f] = g_s[(nbase + n) * NF + f];
        }
        if (t >= 128 && t < 384) {  // scan-A offset partials, 8 threads/feature
            int f = (t - 128) & 31, q = (t - 128) >> 5;
            float a0 = 0.f, a1 = 0.f;
            for (int c = q; c < blk; c += 16) {
                a0 += g_partA[c * NF + f];
                int c2 = c + 8;
                if (c2 < blk) a1 += g_partA[c2 * NF + f];
            }
            su.p2.sredA[q][f] = a0 + a1;
        }
        if (t >= 384 && t < 384 + 24) {  // cred sums, 4 accumulators
            int nd = t - 384;
            int n = nd / 3, d = nd % 3;
            int node = nbase + n;
            int nt = (node + 127) >> 7;
            float a0 = 0.f, a1 = 0.f, a2 = 0.f, a3 = 0.f;
            int ti = 0;
            for (; ti + 4 <= nt; ti += 4) {
                a0 += g_credp[((size_t)(ti + 0) * NND + node) * 3 + d];
                a1 += g_credp[((size_t)(ti + 1) * NND + node) * 3 + d];
                a2 += g_credp[((size_t)(ti + 2) * NND + node) * 3 + d];
                a3 += g_credp[((size_t)(ti + 3) * NND + node) * 3 + d];
            }
            for (; ti < nt; ti++) a0 += g_credp[((size_t)ti * NND + node) * 3 + d];
            su.p2.scred[n][d] = (a0 + a1) + (a2 + a3);
        }
        __syncthreads();
        if (t < 32) {
            float s = 0.f;
#pragma unroll
            for (int q = 0; q < 8; q++) s += su.p2.sredA[q][t];
            su.p2.soff[t] = s;
        }
        __syncthreads();

        for (int idx = t; idx < 8 * NH; idx += 512) {
            int n = idx / NH, c = idx % NH;
            int node = nbase + n;
            float invdeg = (node > 0) ? (1.f / (float)node) : 0.f;
            float hv, nv;
            if (c < NF) {
                hv = x[node * NF + c];
                float S = su.p2.soff[c];
                for (int r = 0; r < n; r++) S += su.p2.sg[r][c];
                nv = invdeg * hv * g_invn[node] * S;
            } else {
                int d = c - NF;
                hv = cent[node * NC + d];
                nv = invdeg * su.p2.scred[n][d];
            }
            su.p2.sH[n][c] = hv;
            su.p2.sN[n][c] = nv;
        }
        __syncthreads();

        int f = t & 63, g = t >> 6;  // g in 0..7 -> node g
        float acc0 = b1[f];
#pragma unroll
        for (int c = 0; c < NH; c++) {
            acc0 += su.p2.sH[g][c] * su.p2.sWs[c][f] + su.p2.sN[g][c] * su.p2.sWn[c][f];
        }
        g_h1[(nbase + g) * H1 + f] = acc0;

        su.p2.sRed[g][f] = acc0;
        __syncthreads();
        if (g < 4) su.p2.sRed[g][f] += su.p2.sRed[g + 4][f];
        __syncthreads();
        if (g < 2) su.p2.sRed[g][f] += su.p2.sRed[g + 2][f];
        __syncthreads();
        if (g == 0) g_partB[blk * H1 + f] = su.p2.sRed[0][f] + su.p2.sRed[1][f];
    }

    gbarrier(&g_bar2);

    // ================= Phase 3: h2 + A/B (blocks 0..255, 8 nodes each) =================
    if (blk < 256) {
        int nbase = blk * 8;
        for (int idx = t; idx < H1 * H2; idx += 512) {
            su.p3.sWs2[idx / H2][idx % H2] = Ws2[idx];
            su.p3.sWn2[idx / H2][idx % H2] = Wn2[idx];
            su.p3.sWm1[idx / H2][idx % H2] = Wm1[idx];
        }
        for (int idx = t; idx < 8 * H1; idx += 512) {
            int r = idx >> 6, c = idx & 63;
            su.p3.sHx[r][c] = g_h1[(nbase + r) * H1 + c];
        }
        {   // scan-B chunk offsets: 8 groups x 4 accumulators -> 32 independent loads
            int grp = t >> 6, c = t & 63;
            int CB = blk;  // 8-node chunks before this block
            float a0 = 0.f, a1 = 0.f, a2 = 0.f, a3 = 0.f;
            for (int base = grp; base < CB; base += 32) {
                a0 += g_partB[base * H1 + c];
                if (base + 8 < CB)  a1 += g_partB[(base + 8) * H1 + c];
                if (base + 16 < CB) a2 += g_partB[(base + 16) * H1 + c];
                if (base + 24 < CB) a3 += g_partB[(base + 24) * H1 + c];
            }
            su.p3.red[grp][c] = (a0 + a1) + (a2 + a3);
        }
        __syncthreads();
        if (t < 64) {
            float s = 0.f;
#pragma unroll
            for (int g = 0; g < 8; g++) s += su.p3.red[g][t];
            su.p3.soffB[t] = s;
        }
        __syncthreads();
        for (int e = t; e < 8 * H1; e += 512) {
            int n = e >> 6, c = e & 63;
            int node = nbase + n;
            float s = su.p3.soffB[c];
            for (int r = 0; r < n; r++) s += su.p3.sHx[r][c];
            float invdeg = (node > 0) ? (1.f / (float)node) : 0.f;
            su.p3.sP1[n][c] = s * invdeg;
        }
        __syncthreads();

        if (t < 256) {
            int ty = t >> 5, f = t & 31;  // 8 nodes x 32 features
            float acc = b2[f];
#pragma unroll 8
            for (int c = 0; c < H1; c++) {
                acc += su.p3.sHx[ty][c] * su.p3.sWs2[c][f] + su.p3.sP1[ty][c] * su.p3.sWn2[c][f];
            }
            su.p3.h2s[ty][f] = acc;
        }
        __syncthreads();
        if (t < 256) {
            int ty = t >> 5, f = t & 31;
            float accA = bm1[f], accB = 0.f;
#pragma unroll
            for (int c = 0; c < H2; c++) {
                float v = su.p3.h2s[ty][c];
                accA += v * su.p3.sWm1[c][f];
                accB += v * su.p3.sWm1[H2 + c][f];
            }
            int node = nbase + ty;
            g_A[node * H2 + f] = accA;
            g_B[node * H2 + f] = accB;
            if (blk == 0 && ty == 0) {
                g_wd[f] = Wm2[f * 2 + 0] - Wm2[f * 2 + 1];
                if (f == 0) g_bd = bm2[0] - bm2[1];
            }
        }
    }

    gbarrier(&g_bar3);

    // ================= Phase 4: edge — one 64(i)x128(j) tile per block =================
    {
        // triangular decode: count per bi = 16 - bi/2, total 272
        int rr = blk;
        int bi = 0;
        while (rr >= 16 - (bi >> 1)) { rr -= 16 - (bi >> 1); bi++; }
        int bj = (bi >> 1) + rr;
        int i0 = bi * 64, j0 = bj * 128;

        {
            const float4* gA4 = (const float4*)(g_A + (size_t)i0 * H2);
            {   // 512 float4 of A
                int v = t;
                int r = v >> 3, c = (v & 7) * 4;
                float4 qa = gA4[v];
                su.p4.sAt[c + 0][r] = qa.x; su.p4.sAt[c + 1][r] = qa.y;
                su.p4.sAt[c + 2][r] = qa.z; su.p4.sAt[c + 3][r] = qa.w;
            }
            const float4* gB4 = (const float4*)(g_B + (size_t)j0 * H2);
#pragma unroll
            for (int u = 0; u < 2; u++) {  // 1024 float4 of B
                int v = t + u * 512;
                int r = v >> 3, c = (v & 7) * 4;
                float4 qb = gB4[v];
                su.p4.sBt[c + 0][r] = qb.x; su.p4.sBt[c + 1][r] = qb.y;
                su.p4.sBt[c + 2][r] = qb.z; su.p4.sBt[c + 3][r] = qb.w;
            }
            if (t < H2) su.p4.swd[t] = g_wd[t];
            if (t == 0) su.p4.sbd = g_bd;
        }
        __syncthreads();

        int tx = t & 31, ty = t >> 5;  // ty: 16 i-groups of 4; tx: 32 j-groups of 4
        float acc[4][4];
#pragma unroll
        for (int a = 0; a < 4; a++)
#pragma unroll
            for (int b = 0; b < 4; b++) acc[a][b] = 0.f;

#pragma unroll
        for (int k = 0; k < H2; k++) {
            float w = su.p4.swd[k];
            float4 a0 = *(const float4*)&su.p4.sAt[k][ty * 4];
            float4 b0 = *(const float4*)&su.p4.sBt[k][tx * 4];
            float av[4] = {a0.x, a0.y, a0.z, a0.w};
            float bv[4] = {b0.x, b0.y, b0.z, b0.w};
#pragma unroll
            for (int a = 0; a < 4; a++)
#pragma unroll
                for (int b = 0; b < 4; b++)
                    acc[a][b] += fmaxf(av[a] + bv[b], 0.f) * w;
        }

        float bd = su.p4.sbd;
#pragma unroll
        for (int a = 0; a < 4; a++) {
            int i = i0 + ty * 4 + a;
            int basei = i * (2 * NND - 1 - i) / 2 - i - 1;  // e = basei + j
            int jlo = j0 + tx * 4;
#pragma unroll
            for (int b = 0; b < 4; b++) {
                int j = jlo + b;
                if (j > i) {
                    float d  = acc[a][b] + bd;  // z0 - z1
                    float ex = __expf(-d);
                    float p0 = __fdividef(1.f, 1.f + ex);
                    float p1 = 1.f - p0;
                    ((float2*)out)[basei + j] = make_float2(p0, p1);
                }
            }
        }
    }
}

// ---------------- launch ----------------
extern "C" void kernel_launch(void* const* d_in, const int* in_sizes, int n_in,
                              void* d_out, int out_size) {
    const float* x    = (const float*)d_in[0];
    const float* cent = (const float*)d_in[1];
    const float* Ws1  = (const float*)d_in[2];
    const float* Wn1  = (const float*)d_in[3];
    const float* b1   = (const float*)d_in[4];
    const float* Ws2  = (const float*)d_in[5];
    const float* Wn2  = (const float*)d_in[6];
    const float* b2   = (const float*)d_in[7];
    const float* Wm1  = (const float*)d_in[8];
    const float* bm1  = (const float*)d_in[9];
    const float* Wm2  = (const float*)d_in[10];
    const float* bm2  = (const float*)d_in[11];
    float* out = (float*)d_out;

    k_fused<<<GRID_N, 512>>>(x, cent, Ws1, Wn1, b1, Ws2, Wn2, b2,
                             Wm1, bm1, Wm2, bm2, out);
}

// round 15
// speedup vs baseline: 1.0228x; 1.0228x over previous
#include <cuda_runtime.h>

#define NND 2048
#define NF  32
#define NC  3
#define NH  35
#define H1  64
#define H2  32
#define GRID_N 272u

// ---------------- scratch (device globals, no allocs) ----------------
__device__ __align__(16) float g_invn[NND];
__device__ __align__(16) float g_s[NND * NF];          // x^2 * invnorm
__device__ __align__(16) float g_partA[256 * NF];      // chunk sums of g_s (8-row chunks)
__device__ __align__(16) float g_credp[16 * NND * 3];  // per-i-tile centroid partials
__device__ __align__(16) float g_h1[NND * H1];
__device__ __align__(16) float g_partB[256 * H1];      // chunk sums of h1 (8-row chunks)
__device__ __align__(16) float g_A[NND * H2];          // h2 @ Wm1[0:32] + bm1
__device__ __align__(16) float g_B[NND * H2];          // h2 @ Wm1[32:64]
__device__ __align__(16) float g_wd[H2];
__device__ float g_bd;

// barrier counters (monotonic across graph replays; no reset needed)
__device__ unsigned g_bar1, g_bar2, g_bar3;

// Arrival: one atomicAdd ticket per block (REDG-cheap).
// Wait: READ-ONLY volatile polling — no RMW contention on the counter line.
__device__ __forceinline__ void gbarrier(unsigned* ctr) {
    __syncthreads();
    if (threadIdx.x == 0) {
        __threadfence();
        unsigned ticket = atomicAdd(ctr, 1u);
        unsigned target = (ticket / GRID_N + 1u) * GRID_N;
        volatile unsigned* vc = (volatile unsigned*)ctr;
        while (*vc < target) { __nanosleep(64); }
        __threadfence();
    }
    __syncthreads();
}

// ---------------- shared-memory union across phases ----------------
struct SP1a { float sm[16][33]; };
struct SP1b { float sc[3][128]; };
struct SP2 {
    float sWs[NH][H1];
    float sWn[NH][H1];
    float sg[8][33];
    float sredA[8][NF];
    float soff[NF];
    float scred[8][3];
    float sH[8][36];
    float sN[8][36];
    float sRed[8][H1 + 1];
};
struct SP3 {
    float sWs2[H1][H2];
    float sWn2[H1][H2];
    float sWm1[H1][H2];
    float sHx[8][H1 + 1];
    float sP1[8][H1 + 1];
    float h2s[8][H2 + 1];
    float soffB[H1];
    float red[8][H1];
};
struct SP4 {
    float sAt[H2][68];    // k-major A tile (64 i + pad)
    float sBt[H2][132];   // k-major B tile (128 j + pad)
    float swd[H2];
    float sbd;
};
union SU { SP1a p1a; SP1b p1b; SP2 p2; SP3 p3; SP4 p4; };

// ================ single fused kernel: 272 blocks x 512 threads ================
__global__ void __launch_bounds__(512, 2) k_fused(
    const float* __restrict__ x, const float* __restrict__ cent,
    const float* __restrict__ Ws1, const float* __restrict__ Wn1,
    const float* __restrict__ b1,
    const float* __restrict__ Ws2, const float* __restrict__ Wn2,
    const float* __restrict__ b2,
    const float* __restrict__ Wm1, const float* __restrict__ bm1,
    const float* __restrict__ Wm2, const float* __restrict__ bm2,
    float* __restrict__ out)
{
    __shared__ SU su;
    int blk = blockIdx.x;
    int t = threadIdx.x;

    // ================= Phase 1 =================
    if (blk < 128) {
        // normsum: 16 nodes/block; emit TWO 8-row chunk partials
        int f = t & 31, r = t >> 5;
        int node = blk * 16 + r;
        float v = x[node * NF + f];
        float sq = v * v;
        float sum = sq;
#pragma unroll
        for (int m = 16; m > 0; m >>= 1) sum += __shfl_xor_sync(0xffffffffu, sum, m);
        float invn = rsqrtf(sum);
        if (f == 0) g_invn[node] = invn;
        float s = sq * invn;
        g_s[node * NF + f] = s;
        su.p1a.sm[r][f] = s;
        __syncthreads();
        // half-local tree reduce (rows 0-7 and 8-15 independently)
        if ((r & 7) < 4) su.p1a.sm[r][f] += su.p1a.sm[r + 4][f];
        __syncthreads();
        if ((r & 7) < 2) su.p1a.sm[r][f] += su.p1a.sm[r + 2][f];
        __syncthreads();
        if ((r & 7) == 0)
            g_partA[(2 * blk + (r >> 3)) * NF + f] = su.p1a.sm[r][f] + su.p1a.sm[r + 1][f];
    } else if (blk < 264) {
        // centroid |diff| tile partials: 136 triangular 128x128 tiles
        int rr = blk - 128;
        int bj = 0;
        while (rr >= bj + 1) { rr -= bj + 1; bj++; }
        int bi = rr;  // bi <= bj
        int i0 = bi * 128;
        if (t < 128) {
            su.p1b.sc[0][t] = cent[(i0 + t) * 3 + 0];
            su.p1b.sc[1][t] = cent[(i0 + t) * 3 + 1];
            su.p1b.sc[2][t] = cent[(i0 + t) * 3 + 2];
        }
        __syncthreads();
        if (t < 128) {
            int j = bj * 128 + t;
            float cj0 = cent[j * 3 + 0], cj1 = cent[j * 3 + 1], cj2 = cent[j * 3 + 2];
            int lim = j - i0;
            if (lim > 128) lim = 128;
            float t0 = 0.f, t1 = 0.f, t2 = 0.f;
#pragma unroll 4
            for (int il = 0; il < lim; il++) {
                float a = su.p1b.sc[0][il], b = su.p1b.sc[1][il], c = su.p1b.sc[2][il];
                t0 += a * fabsf(a - cj0);
                t1 += b * fabsf(b - cj1);
                t2 += c * fabsf(c - cj2);
            }
            size_t o = ((size_t)bi * NND + j) * 3;
            g_credp[o + 0] = t0;
            g_credp[o + 1] = t1;
            g_credp[o + 2] = t2;
        }
    }

    gbarrier(&g_bar1);

    // ================= Phase 2: h1 GEMM (blocks 0..255, 8 nodes each) =================
    if (blk < 256) {
        int nbase = blk * 8;
        for (int idx = t; idx < NH * H1; idx += 512) {
            su.p2.sWs[idx / H1][idx % H1] = Ws1[idx];
            su.p2.sWn[idx / H1][idx % H1] = Wn1[idx];
        }
        {
            int f = t & 31, n = t >> 5;
            if (n < 8) su.p2.sg[n][f] = g_s[(nbase + n) * NF + f];
        }
        if (t >= 128 && t < 384) {  // scan-A offset partials, 8 threads/feature
            int f = (t - 128) & 31, q = (t - 128) >> 5;
            float a0 = 0.f, a1 = 0.f;
            for (int c = q; c < blk; c += 16) {
                a0 += g_partA[c * NF + f];
                int c2 = c + 8;
                if (c2 < blk) a1 += g_partA[c2 * NF + f];
            }
            su.p2.sredA[q][f] = a0 + a1;
        }
        if (t >= 384 && t < 384 + 24) {  // cred sums, 4 accumulators
            int nd = t - 384;
            int n = nd / 3, d = nd % 3;
            int node = nbase + n;
            int nt = (node + 127) >> 7;
            float a0 = 0.f, a1 = 0.f, a2 = 0.f, a3 = 0.f;
            int ti = 0;
            for (; ti + 4 <= nt; ti += 4) {
                a0 += g_credp[((size_t)(ti + 0) * NND + node) * 3 + d];
                a1 += g_credp[((size_t)(ti + 1) * NND + node) * 3 + d];
                a2 += g_credp[((size_t)(ti + 2) * NND + node) * 3 + d];
                a3 += g_credp[((size_t)(ti + 3) * NND + node) * 3 + d];
            }
            for (; ti < nt; ti++) a0 += g_credp[((size_t)ti * NND + node) * 3 + d];
            su.p2.scred[n][d] = (a0 + a1) + (a2 + a3);
        }
        __syncthreads();
        if (t < 32) {
            float s = 0.f;
#pragma unroll
            for (int q = 0; q < 8; q++) s += su.p2.sredA[q][t];
            su.p2.soff[t] = s;
        }
        __syncthreads();

        for (int idx = t; idx < 8 * NH; idx += 512) {
            int n = idx / NH, c = idx % NH;
            int node = nbase + n;
            float invdeg = (node > 0) ? (1.f / (float)node) : 0.f;
            float hv, nv;
            if (c < NF) {
                hv = x[node * NF + c];
                float S = su.p2.soff[c];
                for (int r = 0; r < n; r++) S += su.p2.sg[r][c];
                nv = invdeg * hv * g_invn[node] * S;
            } else {
                int d = c - NF;
                hv = cent[node * NC + d];
                nv = invdeg * su.p2.scred[n][d];
            }
            su.p2.sH[n][c] = hv;
            su.p2.sN[n][c] = nv;
        }
        __syncthreads();

        int f = t & 63, g = t >> 6;  // g in 0..7 -> node g
        float acc0 = b1[f];
#pragma unroll
        for (int c = 0; c < NH; c++) {
            acc0 += su.p2.sH[g][c] * su.p2.sWs[c][f] + su.p2.sN[g][c] * su.p2.sWn[c][f];
        }
        g_h1[(nbase + g) * H1 + f] = acc0;

        su.p2.sRed[g][f] = acc0;
        __syncthreads();
        if (g < 4) su.p2.sRed[g][f] += su.p2.sRed[g + 4][f];
        __syncthreads();
        if (g < 2) su.p2.sRed[g][f] += su.p2.sRed[g + 2][f];
        __syncthreads();
        if (g == 0) g_partB[blk * H1 + f] = su.p2.sRed[0][f] + su.p2.sRed[1][f];
    }

    gbarrier(&g_bar2);

    // ================= Phase 3: h2 + A/B (blocks 0..255, 8 nodes each) =================
    if (blk < 256) {
        int nbase = blk * 8;
        for (int idx = t; idx < H1 * H2; idx += 512) {
            su.p3.sWs2[idx / H2][idx % H2] = Ws2[idx];
            su.p3.sWn2[idx / H2][idx % H2] = Wn2[idx];
            su.p3.sWm1[idx / H2][idx % H2] = Wm1[idx];
        }
        for (int idx = t; idx < 8 * H1; idx += 512) {
            int r = idx >> 6, c = idx & 63;
            su.p3.sHx[r][c] = g_h1[(nbase + r) * H1 + c];
        }
        {   // scan-B chunk offsets: 8 groups x 4 accumulators -> 32 independent loads
            int grp = t >> 6, c = t & 63;
            int CB = blk;  // 8-node chunks before this block
            float a0 = 0.f, a1 = 0.f, a2 = 0.f, a3 = 0.f;
            for (int base = grp; base < CB; base += 32) {
                a0 += g_partB[base * H1 + c];
                if (base + 8 < CB)  a1 += g_partB[(base + 8) * H1 + c];
                if (base + 16 < CB) a2 += g_partB[(base + 16) * H1 + c];
                if (base + 24 < CB) a3 += g_partB[(base + 24) * H1 + c];
            }
            su.p3.red[grp][c] = (a0 + a1) + (a2 + a3);
        }
        __syncthreads();
        if (t < 64) {
            float s = 0.f;
#pragma unroll
            for (int g = 0; g < 8; g++) s += su.p3.red[g][t];
            su.p3.soffB[t] = s;
        }
        __syncthreads();
        for (int e = t; e < 8 * H1; e += 512) {
            int n = e >> 6, c = e & 63;
            int node = nbase + n;
            float s = su.p3.soffB[c];
            for (int r = 0; r < n; r++) s += su.p3.sHx[r][c];
            float invdeg = (node > 0) ? (1.f / (float)node) : 0.f;
            su.p3.sP1[n][c] = s * invdeg;
        }
        __syncthreads();

        if (t < 256) {
            int ty = t >> 5, f = t & 31;  // 8 nodes x 32 features
            float acc = b2[f];
#pragma unroll 8
            for (int c = 0; c < H1; c++) {
                acc += su.p3.sHx[ty][c] * su.p3.sWs2[c][f] + su.p3.sP1[ty][c] * su.p3.sWn2[c][f];
            }
            su.p3.h2s[ty][f] = acc;
        }
        __syncthreads();
        if (t < 256) {
            int ty = t >> 5, f = t & 31;
            float accA = bm1[f], accB = 0.f;
#pragma unroll
            for (int c = 0; c < H2; c++) {
                float v = su.p3.h2s[ty][c];
                accA += v * su.p3.sWm1[c][f];
                accB += v * su.p3.sWm1[H2 + c][f];
            }
            int node = nbase + ty;
            g_A[node * H2 + f] = accA;
            g_B[node * H2 + f] = accB;
            if (blk == 0 && ty == 0) {
                g_wd[f] = Wm2[f * 2 + 0] - Wm2[f * 2 + 1];
                if (f == 0) g_bd = bm2[0] - bm2[1];
            }
        }
    }

    gbarrier(&g_bar3);

    // ================= Phase 4: edge — one 64(i)x128(j) tile per block =================
    {
        // triangular decode: count per bi = 16 - bi/2, total 272
        int rr = blk;
        int bi = 0;
        while (rr >= 16 - (bi >> 1)) { rr -= 16 - (bi >> 1); bi++; }
        int bj = (bi >> 1) + rr;
        int i0 = bi * 64, j0 = bj * 128;

        {
            const float4* gA4 = (const float4*)(g_A + (size_t)i0 * H2);
            {   // 512 float4 of A
                int v = t;
                int r = v >> 3, c = (v & 7) * 4;
                float4 qa = gA4[v];
                su.p4.sAt[c + 0][r] = qa.x; su.p4.sAt[c + 1][r] = qa.y;
                su.p4.sAt[c + 2][r] = qa.z; su.p4.sAt[c + 3][r] = qa.w;
            }
            const float4* gB4 = (const float4*)(g_B + (size_t)j0 * H2);
#pragma unroll
            for (int u = 0; u < 2; u++) {  // 1024 float4 of B
                int v = t + u * 512;
                int r = v >> 3, c = (v & 7) * 4;
                float4 qb = gB4[v];
                su.p4.sBt[c + 0][r] = qb.x; su.p4.sBt[c + 1][r] = qb.y;
                su.p4.sBt[c + 2][r] = qb.z; su.p4.sBt[c + 3][r] = qb.w;
            }
            if (t < H2) su.p4.swd[t] = g_wd[t];
            if (t == 0) su.p4.sbd = g_bd;
        }
        __syncthreads();

        int tx = t & 31, ty = t >> 5;  // ty: 16 i-groups of 4; tx: 32 j-groups of 4
        float acc[4][4];
#pragma unroll
        for (int a = 0; a < 4; a++)
#pragma unroll
            for (int b = 0; b < 4; b++) acc[a][b] = 0.f;

#pragma unroll
        for (int k = 0; k < H2; k++) {
            float w = su.p4.swd[k];
            float4 a0 = *(const float4*)&su.p4.sAt[k][ty * 4];
            float4 b0 = *(const float4*)&su.p4.sBt[k][tx * 4];
            float av[4] = {a0.x, a0.y, a0.z, a0.w};
            float bv[4] = {b0.x, b0.y, b0.z, b0.w};
#pragma unroll
            for (int a = 0; a < 4; a++)
#pragma unroll
                for (int b = 0; b < 4; b++)
                    acc[a][b] += fmaxf(av[a] + bv[b], 0.f) * w;
        }

        float bd = su.p4.sbd;
#pragma unroll
        for (int a = 0; a < 4; a++) {
            int i = i0 + ty * 4 + a;
            int basei = i * (2 * NND - 1 - i) / 2 - i - 1;  // e = basei + j
            int jlo = j0 + tx * 4;
#pragma unroll
            for (int b = 0; b < 4; b++) {
                int j = jlo + b;
                if (j > i) {
                    float d  = acc[a][b] + bd;  // z0 - z1
                    float ex = __expf(-d);
                    float p0 = __fdividef(1.f, 1.f + ex);
                    float p1 = 1.f - p0;
                    ((float2*)out)[basei + j] = make_float2(p0, p1);
                }
            }
        }
    }
}

// ---------------- launch ----------------
extern "C" void kernel_launch(void* const* d_in, const int* in_sizes, int n_in,
                              void* d_out, int out_size) {
    const float* x    = (const float*)d_in[0];
    const float* cent = (const float*)d_in[1];
    const float* Ws1  = (const float*)d_in[2];
    const float* Wn1  = (const float*)d_in[3];
    const float* b1   = (const float*)d_in[4];
    const float* Ws2  = (const float*)d_in[5];
    const float* Wn2  = (const float*)d_in[6];
    const float* b2   = (const float*)d_in[7];
    const float* Wm1  = (const float*)d_in[8];
    const float* bm1  = (const float*)d_in[9];
    const float* Wm2  = (const float*)d_in[10];
    const float* bm2  = (const float*)d_in[11];
    float* out = (float*)d_out;

    k_fused<<<GRID_N, 512>>>(x, cent, Ws1, Wn1, b1, Ws2, Wn2, b2,
                             Wm1, bm1, Wm2, bm2, out);
}

// round 16
// speedup vs baseline: 1.0513x; 1.0279x over previous
#include <cuda_runtime.h>
#include <cuda_fp16.h>

#define NND 2048
#define NF  32
#define NC  3
#define NH  35
#define H1  64
#define H2  32
#define GRID_N 272u

// ---------------- scratch (device globals, no allocs) ----------------
__device__ __align__(16) float g_invn[NND];
__device__ __align__(16) float g_s[NND * NF];          // x^2 * invnorm
__device__ __align__(16) float g_partA[256 * NF];      // chunk sums of g_s (8-row chunks)
__device__ __align__(16) float g_credp[16 * NND * 3];  // per-i-tile centroid partials
__device__ __align__(16) float g_h1[NND * H1];
__device__ __align__(16) float g_partB[256 * H1];      // chunk sums of h1 (8-row chunks)
__device__ __align__(16) float g_A[NND * H2];          // h2 @ Wm1[0:32] + bm1
__device__ __align__(16) float g_B[NND * H2];          // h2 @ Wm1[32:64]
__device__ __align__(16) float g_wd[H2];
__device__ float g_bd;

// barrier counters (monotonic across graph replays; no reset needed)
__device__ unsigned g_bar1, g_bar2, g_bar3;

__device__ __forceinline__ void gbarrier(unsigned* ctr) {
    __syncthreads();
    if (threadIdx.x == 0) {
        __threadfence();
        unsigned ticket = atomicAdd(ctr, 1u);
        unsigned target = (ticket / GRID_N + 1u) * GRID_N;
        volatile unsigned* vc = (volatile unsigned*)ctr;
        while (*vc < target) { __nanosleep(64); }
        __threadfence();
    }
    __syncthreads();
}

// ---------------- shared-memory union across phases ----------------
struct SP1a { float sm[16][33]; };
struct SP1b { float sc[3][128]; };
struct SP2 {
    float sWs[NH][H1];
    float sWn[NH][H1];
    float sg[8][33];
    float sredA[8][NF];
    float soff[NF];
    float scred[8][3];
    float sH[8][36];
    float sN[8][36];
    float sRed[8][H1 + 1];
};
struct SP3 {
    float sWs2[H1][H2];
    float sWn2[H1][H2];
    float sWm1[H1][H2];
    float sHx[8][H1 + 1];
    float sP1[8][H1 + 1];
    float h2s[8][H2 + 1];
    float soffB[H1];
    float red[8][H1];
};
struct SP4 {
    unsigned sAh[16][68];    // half2 (k-pair) A tile: 16 k2 x 64 i (+pad)
    unsigned sBh[16][132];   // half2 B tile: 16 k2 x 128 j (+pad)
    unsigned swh[16];        // half2 wd pairs
    float sbd;
};
union SU { SP1a p1a; SP1b p1b; SP2 p2; SP3 p3; SP4 p4; };

// ================ single fused kernel: 272 blocks x 512 threads ================
__global__ void __launch_bounds__(512, 2) k_fused(
    const float* __restrict__ x, const float* __restrict__ cent,
    const float* __restrict__ Ws1, const float* __restrict__ Wn1,
    const float* __restrict__ b1,
    const float* __restrict__ Ws2, const float* __restrict__ Wn2,
    const float* __restrict__ b2,
    const float* __restrict__ Wm1, const float* __restrict__ bm1,
    const float* __restrict__ Wm2, const float* __restrict__ bm2,
    float* __restrict__ out)
{
    __shared__ SU su;
    int blk = blockIdx.x;
    int t = threadIdx.x;

    // ================= Phase 1 =================
    if (blk < 128) {
        int f = t & 31, r = t >> 5;
        int node = blk * 16 + r;
        float v = x[node * NF + f];
        float sq = v * v;
        float sum = sq;
#pragma unroll
        for (int m = 16; m > 0; m >>= 1) sum += __shfl_xor_sync(0xffffffffu, sum, m);
        float invn = rsqrtf(sum);
        if (f == 0) g_invn[node] = invn;
        float s = sq * invn;
        g_s[node * NF + f] = s;
        su.p1a.sm[r][f] = s;
        __syncthreads();
        if ((r & 7) < 4) su.p1a.sm[r][f] += su.p1a.sm[r + 4][f];
        __syncthreads();
        if ((r & 7) < 2) su.p1a.sm[r][f] += su.p1a.sm[r + 2][f];
        __syncthreads();
        if ((r & 7) == 0)
            g_partA[(2 * blk + (r >> 3)) * NF + f] = su.p1a.sm[r][f] + su.p1a.sm[r + 1][f];
    } else if (blk < 264) {
        int rr = blk - 128;
        int bj = 0;
        while (rr >= bj + 1) { rr -= bj + 1; bj++; }
        int bi = rr;  // bi <= bj
        int i0 = bi * 128;
        if (t < 128) {
            su.p1b.sc[0][t] = cent[(i0 + t) * 3 + 0];
            su.p1b.sc[1][t] = cent[(i0 + t) * 3 + 1];
            su.p1b.sc[2][t] = cent[(i0 + t) * 3 + 2];
        }
        __syncthreads();
        if (t < 128) {
            int j = bj * 128 + t;
            float cj0 = cent[j * 3 + 0], cj1 = cent[j * 3 + 1], cj2 = cent[j * 3 + 2];
            int lim = j - i0;
            if (lim > 128) lim = 128;
            float t0 = 0.f, t1 = 0.f, t2 = 0.f;
#pragma unroll 4
            for (int il = 0; il < lim; il++) {
                float a = su.p1b.sc[0][il], b = su.p1b.sc[1][il], c = su.p1b.sc[2][il];
                t0 += a * fabsf(a - cj0);
                t1 += b * fabsf(b - cj1);
                t2 += c * fabsf(c - cj2);
            }
            size_t o = ((size_t)bi * NND + j) * 3;
            g_credp[o + 0] = t0;
            g_credp[o + 1] = t1;
            g_credp[o + 2] = t2;
        }
    }

    gbarrier(&g_bar1);

    // ================= Phase 2: h1 GEMM (blocks 0..255, 8 nodes each) =================
    if (blk < 256) {
        int nbase = blk * 8;
        for (int idx = t; idx < NH * H1; idx += 512) {
            su.p2.sWs[idx / H1][idx % H1] = Ws1[idx];
            su.p2.sWn[idx / H1][idx % H1] = Wn1[idx];
        }
        {
            int f = t & 31, n = t >> 5;
            if (n < 8) su.p2.sg[n][f] = g_s[(nbase + n) * NF + f];
        }
        if (t >= 128 && t < 384) {
            int f = (t - 128) & 31, q = (t - 128) >> 5;
            float a0 = 0.f, a1 = 0.f;
            for (int c = q; c < blk; c += 16) {
                a0 += g_partA[c * NF + f];
                int c2 = c + 8;
                if (c2 < blk) a1 += g_partA[c2 * NF + f];
            }
            su.p2.sredA[q][f] = a0 + a1;
        }
        if (t >= 384 && t < 384 + 24) {
            int nd = t - 384;
            int n = nd / 3, d = nd % 3;
            int node = nbase + n;
            int nt = (node + 127) >> 7;
            float a0 = 0.f, a1 = 0.f, a2 = 0.f, a3 = 0.f;
            int ti = 0;
            for (; ti + 4 <= nt; ti += 4) {
                a0 += g_credp[((size_t)(ti + 0) * NND + node) * 3 + d];
                a1 += g_credp[((size_t)(ti + 1) * NND + node) * 3 + d];
                a2 += g_credp[((size_t)(ti + 2) * NND + node) * 3 + d];
                a3 += g_credp[((size_t)(ti + 3) * NND + node) * 3 + d];
            }
            for (; ti < nt; ti++) a0 += g_credp[((size_t)ti * NND + node) * 3 + d];
            su.p2.scred[n][d] = (a0 + a1) + (a2 + a3);
        }
        __syncthreads();
        if (t < 32) {
            float s = 0.f;
#pragma unroll
            for (int q = 0; q < 8; q++) s += su.p2.sredA[q][t];
            su.p2.soff[t] = s;
        }
        __syncthreads();

        for (int idx = t; idx < 8 * NH; idx += 512) {
            int n = idx / NH, c = idx % NH;
            int node = nbase + n;
            float invdeg = (node > 0) ? (1.f / (float)node) : 0.f;
            float hv, nv;
            if (c < NF) {
                hv = x[node * NF + c];
                float S = su.p2.soff[c];
                for (int r = 0; r < n; r++) S += su.p2.sg[r][c];
                nv = invdeg * hv * g_invn[node] * S;
            } else {
                int d = c - NF;
                hv = cent[node * NC + d];
                nv = invdeg * su.p2.scred[n][d];
            }
            su.p2.sH[n][c] = hv;
            su.p2.sN[n][c] = nv;
        }
        __syncthreads();

        int f = t & 63, g = t >> 6;
        float acc0 = b1[f];
#pragma unroll
        for (int c = 0; c < NH; c++) {
            acc0 += su.p2.sH[g][c] * su.p2.sWs[c][f] + su.p2.sN[g][c] * su.p2.sWn[c][f];
        }
        g_h1[(nbase + g) * H1 + f] = acc0;

        su.p2.sRed[g][f] = acc0;
        __syncthreads();
        if (g < 4) su.p2.sRed[g][f] += su.p2.sRed[g + 4][f];
        __syncthreads();
        if (g < 2) su.p2.sRed[g][f] += su.p2.sRed[g + 2][f];
        __syncthreads();
        if (g == 0) g_partB[blk * H1 + f] = su.p2.sRed[0][f] + su.p2.sRed[1][f];
    }

    gbarrier(&g_bar2);

    // ================= Phase 3: h2 + A/B (blocks 0..255, 8 nodes each) =================
    if (blk < 256) {
        int nbase = blk * 8;
        for (int idx = t; idx < H1 * H2; idx += 512) {
            su.p3.sWs2[idx / H2][idx % H2] = Ws2[idx];
            su.p3.sWn2[idx / H2][idx % H2] = Wn2[idx];
            su.p3.sWm1[idx / H2][idx % H2] = Wm1[idx];
        }
        for (int idx = t; idx < 8 * H1; idx += 512) {
            int r = idx >> 6, c = idx & 63;
            su.p3.sHx[r][c] = g_h1[(nbase + r) * H1 + c];
        }
        {
            int grp = t >> 6, c = t & 63;
            int CB = blk;
            float a0 = 0.f, a1 = 0.f, a2 = 0.f, a3 = 0.f;
            for (int base = grp; base < CB; base += 32) {
                a0 += g_partB[base * H1 + c];
                if (base + 8 < CB)  a1 += g_partB[(base + 8) * H1 + c];
                if (base + 16 < CB) a2 += g_partB[(base + 16) * H1 + c];
                if (base + 24 < CB) a3 += g_partB[(base + 24) * H1 + c];
            }
            su.p3.red[grp][c] = (a0 + a1) + (a2 + a3);
        }
        __syncthreads();
        if (t < 64) {
            float s = 0.f;
#pragma unroll
            for (int g = 0; g < 8; g++) s += su.p3.red[g][t];
            su.p3.soffB[t] = s;
        }
        __syncthreads();
        for (int e = t; e < 8 * H1; e += 512) {
            int n = e >> 6, c = e & 63;
            int node = nbase + n;
            float s = su.p3.soffB[c];
            for (int r = 0; r < n; r++) s += su.p3.sHx[r][c];
            float invdeg = (node > 0) ? (1.f / (float)node) : 0.f;
            su.p3.sP1[n][c] = s * invdeg;
        }
        __syncthreads();

        if (t < 256) {
            int ty = t >> 5, f = t & 31;
            float acc = b2[f];
#pragma unroll 8
            for (int c = 0; c < H1; c++) {
                acc += su.p3.sHx[ty][c] * su.p3.sWs2[c][f] + su.p3.sP1[ty][c] * su.p3.sWn2[c][f];
            }
            su.p3.h2s[ty][f] = acc;
        }
        __syncthreads();
        if (t < 256) {
            int ty = t >> 5, f = t & 31;
            float accA = bm1[f], accB = 0.f;
#pragma unroll
            for (int c = 0; c < H2; c++) {
                float v = su.p3.h2s[ty][c];
                accA += v * su.p3.sWm1[c][f];
                accB += v * su.p3.sWm1[H2 + c][f];
            }
            int node = nbase + ty;
            g_A[node * H2 + f] = accA;
            g_B[node * H2 + f] = accB;
            if (blk == 0 && ty == 0) {
                g_wd[f] = Wm2[f * 2 + 0] - Wm2[f * 2 + 1];
                if (f == 0) g_bd = bm2[0] - bm2[1];
            }
        }
    }

    gbarrier(&g_bar3);

    // ================= Phase 4: edge (f16x2 packed along k) — one 64x128 tile per block =====
    {
        int rr = blk;
        int bi = 0;
        while (rr >= 16 - (bi >> 1)) { rr -= 16 - (bi >> 1); bi++; }
        int bj = (bi >> 1) + rr;
        int i0 = bi * 64, j0 = bj * 128;

        {
            const float4* gA4 = (const float4*)(g_A + (size_t)i0 * H2);
            {
                int r = t >> 3, q = t & 7;
                float4 qa = gA4[t];
                __half2 h0 = __floats2half2_rn(qa.x, qa.y);
                __half2 h1v = __floats2half2_rn(qa.z, qa.w);
                su.p4.sAh[2 * q + 0][r] = *(unsigned*)&h0;
                su.p4.sAh[2 * q + 1][r] = *(unsigned*)&h1v;
            }
            const float4* gB4 = (const float4*)(g_B + (size_t)j0 * H2);
#pragma unroll
            for (int u = 0; u < 2; u++) {
                int vv = t + u * 512;
                int r = vv >> 3, q = vv & 7;
                float4 qb = gB4[vv];
                __half2 h0 = __floats2half2_rn(qb.x, qb.y);
                __half2 h1v = __floats2half2_rn(qb.z, qb.w);
                su.p4.sBh[2 * q + 0][r] = *(unsigned*)&h0;
                su.p4.sBh[2 * q + 1][r] = *(unsigned*)&h1v;
            }
            if (t < 16) {
                __half2 hw = __floats2half2_rn(g_wd[2 * t], g_wd[2 * t + 1]);
                su.p4.swh[t] = *(unsigned*)&hw;
            }
            if (t == 0) su.p4.sbd = g_bd;
        }
        __syncthreads();

        int tx = t & 31, ty = t >> 5;  // ty: 16 i-groups of 4; tx: 32 j-groups of 4
        __half2 acc[4][4];
        const __half2 hzero = __float2half2_rn(0.f);
#pragma unroll
        for (int a = 0; a < 4; a++)
#pragma unroll
            for (int b = 0; b < 4; b++) acc[a][b] = hzero;

#pragma unroll
        for (int k2 = 0; k2 < 16; k2++) {
            unsigned wu = su.p4.swh[k2];
            __half2 w2 = *(__half2*)&wu;
            uint4 au = *(const uint4*)&su.p4.sAh[k2][ty * 4];   // broadcast per warp
            uint4 bu = *(const uint4*)&su.p4.sBh[k2][tx * 4];
            __half2 av[4] = {*(__half2*)&au.x, *(__half2*)&au.y, *(__half2*)&au.z, *(__half2*)&au.w};
            __half2 bv[4] = {*(__half2*)&bu.x, *(__half2*)&bu.y, *(__half2*)&bu.z, *(__half2*)&bu.w};
#pragma unroll
            for (int a = 0; a < 4; a++)
#pragma unroll
                for (int b = 0; b < 4; b++) {
                    __half2 s = __hmax2(__hadd2(av[a], bv[b]), hzero);
                    acc[a][b] = __hfma2(s, w2, acc[a][b]);
                }
        }

        float bd = su.p4.sbd;
#pragma unroll
        for (int a = 0; a < 4; a++) {
            int i = i0 + ty * 4 + a;
            int basei = i * (2 * NND - 1 - i) / 2 - i - 1;  // e = basei + j
            int jlo = j0 + tx * 4;
#pragma unroll
            for (int b = 0; b < 4; b++) {
                int j = jlo + b;
                if (j > i) {
                    float2 lh = __half22float2(acc[a][b]);
                    float d  = lh.x + lh.y + bd;  // z0 - z1
                    float ex = __expf(-d);
                    float p0 = __fdividef(1.f, 1.f + ex);
                    float p1 = 1.f - p0;
                    ((float2*)out)[basei + j] = make_float2(p0, p1);
                }
            }
        }
    }
}

// ---------------- launch ----------------
extern "C" void kernel_launch(void* const* d_in, const int* in_sizes, int n_in,
                              void* d_out, int out_size) {
    const float* x    = (const float*)d_in[0];
    const float* cent = (const float*)d_in[1];
    const float* Ws1  = (const float*)d_in[2];
    const float* Wn1  = (const float*)d_in[3];
    const float* b1   = (const float*)d_in[4];
    const float* Ws2  = (const float*)d_in[5];
    const float* Wn2  = (const float*)d_in[6];
    const float* b2   = (const float*)d_in[7];
    const float* Wm1  = (const float*)d_in[8];
    const float* bm1  = (const float*)d_in[9];
    const float* Wm2  = (const float*)d_in[10];
    const float* bm2  = (const float*)d_in[11];
    float* out = (float*)d_out;

    k_fused<<<GRID_N, 512>>>(x, cent, Ws1, Wn1, b1, Ws2, Wn2, b2,
                             Wm1, bm1, Wm2, bm2, out);
}